// round 2
// baseline (speedup 1.0000x reference)
#include <cuda_runtime.h>

// Problem constants (fixed by the dataset: emb [8,8,1024,1024] f32, gt_seg [8,1024,1024] i32)
#define B_      8
#define D_      8
#define HW_     (1024 * 1024)
#define NP4_    (HW_ / 4)
#define C_      5
#define CTAS_   18          // CTAs per batch -> 144 total blocks (<=148 SMs, 1 wave)
#define THREADS_ 256
#define NVALS_  50          // 40 sums (c-major) + 5 sumsq + 5 counts

typedef unsigned long long u64;

// Fixed-slot per-block partials: deterministic (no float atomics), no allocation.
__device__ float g_partials[B_][CTAS_][NVALS_];

// ---- packed f32x2 helpers (Blackwell FFMA2 path, PTX-only) ----
__device__ __forceinline__ u64 pk2(float lo, float hi) {
    u64 r; asm("mov.b64 %0, {%1, %2};" : "=l"(r) : "f"(lo), "f"(hi)); return r;
}
__device__ __forceinline__ float2 upk2(u64 v) {
    float2 f; asm("mov.b64 {%0, %1}, %2;" : "=f"(f.x), "=f"(f.y) : "l"(v)); return f;
}
__device__ __forceinline__ void fma2(u64& a, u64 m, u64 v) {   // a += m * v (per 32-bit lane)
    asm("fma.rn.f32x2 %0, %1, %2, %0;" : "+l"(a) : "l"(m), "l"(v));
}
__device__ __forceinline__ void add2(u64& a, u64 v) {          // a += v
    asm("add.rn.f32x2 %0, %0, %1;" : "+l"(a) : "l"(v));
}

// Pass 1: per-(batch, block) partial reduction of counts / sums / sum-of-squares per cluster.
// Two pixel streams packed in each f32x2 accumulator (even/odd pixel phases).
__global__ void __launch_bounds__(THREADS_, 1)
lane_loss_partial_kernel(const float* __restrict__ emb, const int* __restrict__ seg) {
    const int b = blockIdx.y;
    const int4*   __restrict__ seg4 = (const int4*)(seg + (size_t)b * HW_);
    const float4* __restrict__ e4   = (const float4*)(emb + (size_t)b * D_ * HW_);

    u64 accS[C_][D_];
    u64 accQ[C_], accC[C_];
#pragma unroll
    for (int c = 0; c < C_; c++) {
        accQ[c] = 0ull; accC[c] = 0ull;
#pragma unroll
        for (int d = 0; d < D_; d++) accS[c][d] = 0ull;
    }

    for (int i = blockIdx.x * THREADS_ + threadIdx.x; i < NP4_; i += CTAS_ * THREADS_) {
        const int4 s = seg4[i];

        u64 m01[C_], m23[C_];
#pragma unroll
        for (int c = 0; c < C_; c++) {
            m01[c] = pk2(s.x == c ? 1.f : 0.f, s.y == c ? 1.f : 0.f);
            m23[c] = pk2(s.z == c ? 1.f : 0.f, s.w == c ? 1.f : 0.f);
        }

        u64 q01 = 0ull, q23 = 0ull;
#pragma unroll
        for (int d = 0; d < D_; d++) {
            const float4 v = e4[(size_t)d * NP4_ + i];
            const u64 v01 = pk2(v.x, v.y);
            const u64 v23 = pk2(v.z, v.w);
            fma2(q01, v01, v01);   // q += x*x
            fma2(q23, v23, v23);
#pragma unroll
            for (int c = 0; c < C_; c++) {
                fma2(accS[c][d], m01[c], v01);   // masked sum accumulate
                fma2(accS[c][d], m23[c], v23);
            }
        }
#pragma unroll
        for (int c = 0; c < C_; c++) {
            fma2(accQ[c], m01[c], q01);
            fma2(accQ[c], m23[c], q23);
            add2(accC[c], m01[c]);               // masks are exactly 0/1 -> exact counts
            add2(accC[c], m23[c]);
        }
    }

    // Collapse the two packed pixel streams -> 50 per-thread scalars.
    float vals[NVALS_];
#pragma unroll
    for (int c = 0; c < C_; c++) {
#pragma unroll
        for (int d = 0; d < D_; d++) { float2 f = upk2(accS[c][d]); vals[c * D_ + d] = f.x + f.y; }
    }
#pragma unroll
    for (int c = 0; c < C_; c++) { float2 f = upk2(accQ[c]); vals[40 + c] = f.x + f.y; }
#pragma unroll
    for (int c = 0; c < C_; c++) { float2 f = upk2(accC[c]); vals[45 + c] = f.x + f.y; }

    // Intra-warp butterfly reduce (all 32 lanes active everywhere).
#pragma unroll
    for (int k = 0; k < NVALS_; k++) {
#pragma unroll
        for (int off = 16; off > 0; off >>= 1)
            vals[k] += __shfl_xor_sync(0xffffffffu, vals[k], off);
    }

    __shared__ float red[THREADS_ / 32][NVALS_];
    const int warp = threadIdx.x >> 5, lane = threadIdx.x & 31;
    if (lane == 0) {
#pragma unroll
        for (int k = 0; k < NVALS_; k++) red[warp][k] = vals[k];
    }
    __syncthreads();
    if (threadIdx.x < NVALS_) {
        float s = 0.f;
#pragma unroll
        for (int w = 0; w < THREADS_ / 32; w++) s += red[w][threadIdx.x];
        g_partials[b][blockIdx.x][threadIdx.x] = s;
    }
}

// Pass 2: deterministic finalize in double. sigma_v=0.5, sigma_d=3.0.
__global__ void lane_loss_finalize_kernel(float* __restrict__ out) {
    __shared__ double sv[B_][NVALS_];
    __shared__ double lossb[B_];
    const int t = threadIdx.x;

    if (t < B_ * NVALS_) {
        const int b = t / NVALS_, k = t % NVALS_;
        double s = 0.0;
        for (int j = 0; j < CTAS_; j++) s += (double)g_partials[b][j][k];
        sv[b][k] = s;
    }
    __syncthreads();

    if (t < B_) {
        const int b = t;
        double mean[C_][D_];
        double var_loss = 0.0;
        for (int c = 0; c < C_; c++) {
            const double cn = sv[b][45 + c];
            const double q  = sv[b][40 + c];
            double m2 = 0.0;
            for (int d = 0; d < D_; d++) {
                const double sm = sv[b][c * D_ + d];
                const double m  = sm / cn;
                mean[c][d] = m;
                m2 += sm * m;                       // = count * ||mean||^2
            }
            double ssv = q - m2;                     // sum of squared residuals
            if (ssv < 0.0) ssv = 0.0;
            const double r = sqrt(ssv) - 0.5;        // SIGMA_V
            if (r > 0.0) var_loss += r;
        }
        var_loss /= (double)C_;

        double dist = 0.0;
        for (int i = 0; i < C_; i++)
            for (int j = 0; j < C_; j++) {
                if (i == j) continue;
                double d2 = 0.0;
                for (int d = 0; d < D_; d++) {
                    const double df = mean[i][d] - mean[j][d];
                    d2 += df * df;
                }
                const double h = 3.0 - sqrt(d2);     // SIGMA_D; off-diag of sqrt(d2+eye)=sqrt(d2)
                if (h > 0.0) dist += h;
            }
        dist /= (double)(C_ * (C_ - 1));
        lossb[b] = var_loss + dist;
    }
    __syncthreads();

    if (t == 0) {
        double s = 0.0;
        for (int b = 0; b < B_; b++) s += lossb[b];
        out[0] = (float)(s / (double)B_);
    }
}

extern "C" void kernel_launch(void* const* d_in, const int* in_sizes, int n_in,
                              void* d_out, int out_size) {
    const float* emb = (const float*)d_in[0];   // [8, 8, 1024, 1024] f32
    const int*   seg = (const int*)d_in[1];     // [8, 1024, 1024] i32
    (void)in_sizes; (void)n_in; (void)out_size;

    dim3 grid(CTAS_, B_);
    lane_loss_partial_kernel<<<grid, THREADS_>>>(emb, seg);
    lane_loss_finalize_kernel<<<1, 512>>>((float*)d_out);
}

// round 4
// speedup vs baseline: 1.5222x; 1.5222x over previous
#include <cuda_runtime.h>

// Problem constants (fixed by the dataset: emb [8,8,1024,1024] f32, gt_seg [8,1024,1024] i32)
#define B_      8
#define D_      8
#define HW_     (1024 * 1024)
#define NP4_    (HW_ / 4)
#define C_      5
#define CTAS_   18          // CTAs per batch -> 144 total blocks (<=148 SMs, 1 wave)
#define THREADS_ 256
#define NVALS_  50          // 40 sums (c-major) + 5 sumsq + 5 counts
#define NPAIRS_ (C_ * (C_ - 1))   // 20 ordered pairs

typedef unsigned long long u64;

// Fixed-slot per-block partials: deterministic (no float atomics), no allocation.
__device__ float g_partials[B_][CTAS_][NVALS_];

// ---- packed f32x2 helpers (Blackwell FFMA2 path, PTX-only) ----
__device__ __forceinline__ u64 pk2(float lo, float hi) {
    u64 r; asm("mov.b64 %0, {%1, %2};" : "=l"(r) : "f"(lo), "f"(hi)); return r;
}
__device__ __forceinline__ float2 upk2(u64 v) {
    float2 f; asm("mov.b64 {%0, %1}, %2;" : "=f"(f.x), "=f"(f.y) : "l"(v)); return f;
}
__device__ __forceinline__ void fma2(u64& a, u64 m, u64 v) {   // a += m * v (per 32-bit lane)
    asm("fma.rn.f32x2 %0, %1, %2, %0;" : "+l"(a) : "l"(m), "l"(v));
}
__device__ __forceinline__ void add2(u64& a, u64 v) {          // a += v
    asm("add.rn.f32x2 %0, %0, %1;" : "+l"(a) : "l"(v));
}

// Pass 1: per-(batch, block) partial reduction of counts / sums / sum-of-squares per cluster.
// Two pixel streams packed in each f32x2 accumulator (even/odd pixel phases).
__global__ void __launch_bounds__(THREADS_, 1)
lane_loss_partial_kernel(const float* __restrict__ emb, const int* __restrict__ seg) {
    const int b = blockIdx.y;
    const int4*   __restrict__ seg4 = (const int4*)(seg + (size_t)b * HW_);
    const float4* __restrict__ e4   = (const float4*)(emb + (size_t)b * D_ * HW_);

    u64 accS[C_][D_];
    u64 accQ[C_], accC[C_];
#pragma unroll
    for (int c = 0; c < C_; c++) {
        accQ[c] = 0ull; accC[c] = 0ull;
#pragma unroll
        for (int d = 0; d < D_; d++) accS[c][d] = 0ull;
    }

    for (int i = blockIdx.x * THREADS_ + threadIdx.x; i < NP4_; i += CTAS_ * THREADS_) {
        const int4 s = seg4[i];

        u64 m01[C_], m23[C_];
#pragma unroll
        for (int c = 0; c < C_; c++) {
            m01[c] = pk2(s.x == c ? 1.f : 0.f, s.y == c ? 1.f : 0.f);
            m23[c] = pk2(s.z == c ? 1.f : 0.f, s.w == c ? 1.f : 0.f);
        }

        u64 q01 = 0ull, q23 = 0ull;
#pragma unroll
        for (int d = 0; d < D_; d++) {
            const float4 v = e4[(size_t)d * NP4_ + i];
            const u64 v01 = pk2(v.x, v.y);
            const u64 v23 = pk2(v.z, v.w);
            fma2(q01, v01, v01);   // q += x*x
            fma2(q23, v23, v23);
#pragma unroll
            for (int c = 0; c < C_; c++) {
                fma2(accS[c][d], m01[c], v01);   // masked sum accumulate
                fma2(accS[c][d], m23[c], v23);
            }
        }
#pragma unroll
        for (int c = 0; c < C_; c++) {
            fma2(accQ[c], m01[c], q01);
            fma2(accQ[c], m23[c], q23);
            add2(accC[c], m01[c]);               // masks are exactly 0/1 -> exact counts
            add2(accC[c], m23[c]);
        }
    }

    // Collapse the two packed pixel streams -> 50 per-thread scalars.
    float vals[NVALS_];
#pragma unroll
    for (int c = 0; c < C_; c++) {
#pragma unroll
        for (int d = 0; d < D_; d++) { float2 f = upk2(accS[c][d]); vals[c * D_ + d] = f.x + f.y; }
    }
#pragma unroll
    for (int c = 0; c < C_; c++) { float2 f = upk2(accQ[c]); vals[40 + c] = f.x + f.y; }
#pragma unroll
    for (int c = 0; c < C_; c++) { float2 f = upk2(accC[c]); vals[45 + c] = f.x + f.y; }

    // Intra-warp butterfly reduce (all 32 lanes active everywhere).
#pragma unroll
    for (int k = 0; k < NVALS_; k++) {
#pragma unroll
        for (int off = 16; off > 0; off >>= 1)
            vals[k] += __shfl_xor_sync(0xffffffffu, vals[k], off);
    }

    __shared__ float red[THREADS_ / 32][NVALS_];
    const int warp = threadIdx.x >> 5, lane = threadIdx.x & 31;
    if (lane == 0) {
#pragma unroll
        for (int k = 0; k < NVALS_; k++) red[warp][k] = vals[k];
    }
    __syncthreads();
    if (threadIdx.x < NVALS_) {
        float s = 0.f;
#pragma unroll
        for (int w = 0; w < THREADS_ / 32; w++) s += red[w][threadIdx.x];
        g_partials[b][blockIdx.x][threadIdx.x] = s;
    }
}

// Pass 2: deterministic FP32 finalize, parallelized across threads.
// sigma_v=0.5, sigma_d=3.0.  Numerics: loss ~= 1268 (var term sqrt(1.6e6) dominates);
// q - count*||mean||^2 has no cancellation (1.6e6 vs ~1.6); fp32 rel err ~1e-7 << 1e-3 tol.
__global__ void lane_loss_finalize_kernel(float* __restrict__ out) {
    __shared__ float sv[B_][NVALS_];                 // reduced 50 scalars per batch
    __shared__ float mean_s[B_][C_][D_];
    __shared__ float var_s[B_][C_];                  // relu(sqrt(ss) - 0.5)
    __shared__ float hinge_s[B_][NPAIRS_];           // relu(3 - d) per ordered pair
    const int t = threadIdx.x;

    // Stage 1: reduce the 18 CTA partials -> sv  (400 threads)
    if (t < B_ * NVALS_) {
        const int b = t / NVALS_, k = t % NVALS_;
        float s = 0.f;
#pragma unroll
        for (int j = 0; j < CTAS_; j++) s += g_partials[b][j][k];
        sv[b][k] = s;
    }
    __syncthreads();

    // Stage 2: means (320 threads)
    if (t < B_ * C_ * D_) {
        const int b = t / (C_ * D_);
        const int c = (t / D_) % C_;
        const int d = t % D_;
        mean_s[b][c][d] = sv[b][c * D_ + d] / sv[b][45 + c];
    }
    __syncthreads();

    // Stage 3a: variance terms (40 threads)
    if (t < B_ * C_) {
        const int b = t / C_, c = t % C_;
        float m2 = 0.f;
#pragma unroll
        for (int d = 0; d < D_; d++) m2 += sv[b][c * D_ + d] * mean_s[b][c][d];
        float ssv = sv[b][40 + c] - m2;              // sum of squared residuals
        if (ssv < 0.f) ssv = 0.f;
        const float r = sqrtf(ssv) - 0.5f;           // SIGMA_V
        var_s[b][c] = r > 0.f ? r : 0.f;
    }

    // Stage 3b: hinge terms on ordered pairs i != j (160 threads)
    if (t < B_ * NPAIRS_) {
        const int b = t / NPAIRS_, p = t % NPAIRS_;
        const int i = p / (C_ - 1);
        int j = p % (C_ - 1);
        if (j >= i) j++;                             // skip diagonal
        float d2 = 0.f;
#pragma unroll
        for (int d = 0; d < D_; d++) {
            const float df = mean_s[b][i][d] - mean_s[b][j][d];
            d2 += df * df;
        }
        const float h = 3.0f - sqrtf(d2);            // SIGMA_D
        hinge_s[b][p] = h > 0.f ? h : 0.f;
    }
    __syncthreads();

    // Stage 4: deterministic serial combine (200 fp32 adds — negligible)
    if (t == 0) {
        float total = 0.f;
        for (int b = 0; b < B_; b++) {
            float v = 0.f;
#pragma unroll
            for (int c = 0; c < C_; c++) v += var_s[b][c];
            float dl = 0.f;
#pragma unroll
            for (int p = 0; p < NPAIRS_; p++) dl += hinge_s[b][p];
            total += v / (float)C_ + dl / (float)NPAIRS_;
        }
        out[0] = total / (float)B_;
    }
}

extern "C" void kernel_launch(void* const* d_in, const int* in_sizes, int n_in,
                              void* d_out, int out_size) {
    const float* emb = (const float*)d_in[0];   // [8, 8, 1024, 1024] f32
    const int*   seg = (const int*)d_in[1];     // [8, 1024, 1024] i32
    (void)in_sizes; (void)n_in; (void)out_size;

    dim3 grid(CTAS_, B_);
    lane_loss_partial_kernel<<<grid, THREADS_>>>(emb, seg);
    lane_loss_finalize_kernel<<<1, 512>>>((float*)d_out);
}

// round 9
// speedup vs baseline: 1.8336x; 1.2046x over previous
#include <cuda_runtime.h>

// Problem constants (fixed by the dataset: emb [8,8,1024,1024] f32, gt_seg [8,1024,1024] i32)
#define B_      8
#define D_      8
#define HW_     (1024 * 1024)
#define NP4_    (HW_ / 4)
#define C_      5
#define CTAS_   18            // CTAs per batch -> 144 total blocks (<=148 SMs, 1 wave)
#define THREADS_ 256
#define TOTAL_CTAS_ (CTAS_ * B_)
#define NVALS_  50
#define NPAIRS_ (C_ * (C_ - 1))   // 20 ordered pairs

// NVALS layout per (batch, block):
//   [0..31]  S[c][d]  for c<4           (masked sums)
//   [32..39] T[d]                       (total sums, cluster 4 derived)
//   [40..43] q_c      for c<4           (masked sum of squares)
//   [44]     qT                         (total sum of squares)
//   [45..48] cnt_c    for c<4
//   [49]     n                          (pixels processed by this block)

typedef unsigned long long u64;

__device__ float g_partials[B_][CTAS_][NVALS_];
__device__ unsigned int g_done;   // zero-initialized; last block resets to 0 each launch

// ---- packed f32x2 helpers (Blackwell FFMA2 path, PTX-only) ----
__device__ __forceinline__ u64 pk2(float lo, float hi) {
    u64 r; asm("mov.b64 %0, {%1, %2};" : "=l"(r) : "f"(lo), "f"(hi)); return r;
}
__device__ __forceinline__ float2 upk2(u64 v) {
    float2 f; asm("mov.b64 {%0, %1}, %2;" : "=f"(f.x), "=f"(f.y) : "l"(v)); return f;
}
__device__ __forceinline__ void fma2(u64& a, u64 m, u64 v) {   // a += m * v (per 32-bit lane)
    asm("fma.rn.f32x2 %0, %1, %2, %0;" : "+l"(a) : "l"(m), "l"(v));
}
__device__ __forceinline__ void add2(u64& a, u64 v) {          // a += v
    asm("add.rn.f32x2 %0, %0, %1;" : "+l"(a) : "l"(v));
}

__global__ void __launch_bounds__(THREADS_, 1)
lane_loss_fused_kernel(const float* __restrict__ emb, const int* __restrict__ seg,
                       float* __restrict__ out) {
    const int b = blockIdx.y;
    const int4*   __restrict__ seg4 = (const int4*)(seg + (size_t)b * HW_);
    const float4* __restrict__ e4   = (const float4*)(emb + (size_t)b * D_ * HW_);

    // ---------------- Pass 1: streaming partial reduction ----------------
    u64 accS[4][D_];     // masked sums, clusters 0..3
    u64 accT[D_];        // total sums
    u64 accQ[4];         // masked sum-of-squares, clusters 0..3
    u64 accQT;           // total sum-of-squares
    u64 accC[4];         // counts 0..3 (exact in f32)
    int n_it = 0;
#pragma unroll
    for (int c = 0; c < 4; c++) { accQ[c] = 0ull; accC[c] = 0ull;
#pragma unroll
        for (int d = 0; d < D_; d++) accS[c][d] = 0ull; }
#pragma unroll
    for (int d = 0; d < D_; d++) accT[d] = 0ull;
    accQT = 0ull;

    for (int i = blockIdx.x * THREADS_ + threadIdx.x; i < NP4_; i += CTAS_ * THREADS_) {
        const int4 s = __ldcs(&seg4[i]);
        n_it++;

        u64 m01[4], m23[4];
#pragma unroll
        for (int c = 0; c < 4; c++) {
            m01[c] = pk2(s.x == c ? 1.f : 0.f, s.y == c ? 1.f : 0.f);
            m23[c] = pk2(s.z == c ? 1.f : 0.f, s.w == c ? 1.f : 0.f);
        }

        u64 q01 = 0ull, q23 = 0ull;
#pragma unroll
        for (int d = 0; d < D_; d++) {
            const float4 v = __ldcs(&e4[(size_t)d * NP4_ + i]);
            const u64 v01 = pk2(v.x, v.y);
            const u64 v23 = pk2(v.z, v.w);
            fma2(q01, v01, v01);
            fma2(q23, v23, v23);
            add2(accT[d], v01);
            add2(accT[d], v23);
#pragma unroll
            for (int c = 0; c < 4; c++) {
                fma2(accS[c][d], m01[c], v01);
                fma2(accS[c][d], m23[c], v23);
            }
        }
#pragma unroll
        for (int c = 0; c < 4; c++) {
            fma2(accQ[c], m01[c], q01);
            fma2(accQ[c], m23[c], q23);
            add2(accC[c], m01[c]);
            add2(accC[c], m23[c]);
        }
        add2(accQT, q01);
        add2(accQT, q23);
    }

    // Collapse packed lanes -> 50 per-thread scalars
    float vals[NVALS_];
#pragma unroll
    for (int c = 0; c < 4; c++)
#pragma unroll
        for (int d = 0; d < D_; d++) { float2 f = upk2(accS[c][d]); vals[c * D_ + d] = f.x + f.y; }
#pragma unroll
    for (int d = 0; d < D_; d++) { float2 f = upk2(accT[d]); vals[32 + d] = f.x + f.y; }
#pragma unroll
    for (int c = 0; c < 4; c++) { float2 f = upk2(accQ[c]); vals[40 + c] = f.x + f.y; }
    { float2 f = upk2(accQT); vals[44] = f.x + f.y; }
#pragma unroll
    for (int c = 0; c < 4; c++) { float2 f = upk2(accC[c]); vals[45 + c] = f.x + f.y; }
    vals[49] = (float)(n_it * 4);

    // Intra-warp butterfly reduce
#pragma unroll
    for (int k = 0; k < NVALS_; k++)
#pragma unroll
        for (int off = 16; off > 0; off >>= 1)
            vals[k] += __shfl_xor_sync(0xffffffffu, vals[k], off);

    __shared__ float red[THREADS_ / 32][NVALS_];
    const int warp = threadIdx.x >> 5, lane = threadIdx.x & 31;
    if (lane == 0)
#pragma unroll
        for (int k = 0; k < NVALS_; k++) red[warp][k] = vals[k];
    __syncthreads();
    if (threadIdx.x < NVALS_) {
        float s = 0.f;
#pragma unroll
        for (int w = 0; w < THREADS_ / 32; w++) s += red[w][threadIdx.x];
        g_partials[b][blockIdx.x][threadIdx.x] = s;
    }

    // ---------------- Last-block-done handoff ----------------
    __shared__ unsigned int amLast;
    __threadfence();                       // release g_partials writes
    if (threadIdx.x == 0) {
        unsigned int v = atomicAdd(&g_done, 1u);
        amLast = (v == TOTAL_CTAS_ - 1) ? 1u : 0u;
    }
    __syncthreads();
    if (!amLast) return;
    __threadfence();                       // acquire other blocks' g_partials
    if (threadIdx.x == 0) g_done = 0;      // reset for next launch / graph replay

    // ---------------- Pass 2: finalize (fp32, deterministic) ----------------
    // Loss ~1268; q - count*||mean||^2 has no cancellation; fp32 rel err ~1e-7 << 1e-3 tol.
    __shared__ float sv[B_][NVALS_];
    __shared__ float mean_s[B_][C_][D_];
    __shared__ float sum_s[B_][C_][D_];    // per-cluster sums incl. derived c=4
    __shared__ float var_s[B_][C_];
    __shared__ float hinge_s[B_][NPAIRS_];
    const int t = threadIdx.x;

    // Stage 1: reduce 18 CTA partials
    for (int idx = t; idx < B_ * NVALS_; idx += THREADS_) {
        const int bb = idx / NVALS_, k = idx % NVALS_;
        float s = 0.f;
#pragma unroll
        for (int j = 0; j < CTAS_; j++) s += g_partials[bb][j][k];
        sv[bb][k] = s;
    }
    __syncthreads();

    // Stage 2: per-cluster sums (derive c=4) and means
    for (int idx = t; idx < B_ * C_ * D_; idx += THREADS_) {
        const int bb = idx / (C_ * D_);
        const int c  = (idx / D_) % C_;
        const int d  = idx % D_;
        float sm, cn;
        if (c < 4) {
            sm = sv[bb][c * D_ + d];
            cn = sv[bb][45 + c];
        } else {
            sm = sv[bb][32 + d] - (sv[bb][0 * D_ + d] + sv[bb][1 * D_ + d] +
                                   sv[bb][2 * D_ + d] + sv[bb][3 * D_ + d]);
            cn = sv[bb][49] - (sv[bb][45] + sv[bb][46] + sv[bb][47] + sv[bb][48]);
        }
        sum_s[bb][c][d]  = sm;
        mean_s[bb][c][d] = sm / cn;
    }
    __syncthreads();

    // Stage 3a: variance terms
    for (int idx = t; idx < B_ * C_; idx += THREADS_) {
        const int bb = idx / C_, c = idx % C_;
        float q;
        if (c < 4) q = sv[bb][40 + c];
        else       q = sv[bb][44] - (sv[bb][40] + sv[bb][41] + sv[bb][42] + sv[bb][43]);
        float m2 = 0.f;
#pragma unroll
        for (int d = 0; d < D_; d++) m2 += sum_s[bb][c][d] * mean_s[bb][c][d];
        float ssv = q - m2;
        if (ssv < 0.f) ssv = 0.f;
        const float r = sqrtf(ssv) - 0.5f;           // SIGMA_V
        var_s[bb][c] = r > 0.f ? r : 0.f;
    }

    // Stage 3b: hinge terms on ordered pairs i != j
    for (int idx = t; idx < B_ * NPAIRS_; idx += THREADS_) {
        const int bb = idx / NPAIRS_, p = idx % NPAIRS_;
        const int i = p / (C_ - 1);
        int j = p % (C_ - 1);
        if (j >= i) j++;
        float d2 = 0.f;
#pragma unroll
        for (int d = 0; d < D_; d++) {
            const float df = mean_s[bb][i][d] - mean_s[bb][j][d];
            d2 += df * df;
        }
        const float h = 3.0f - sqrtf(d2);            // SIGMA_D
        hinge_s[bb][p] = h > 0.f ? h : 0.f;
    }
    __syncthreads();

    // Stage 4: deterministic serial combine
    if (t == 0) {
        float total = 0.f;
        for (int bb = 0; bb < B_; bb++) {
            float v = 0.f;
#pragma unroll
            for (int c = 0; c < C_; c++) v += var_s[bb][c];
            float dl = 0.f;
#pragma unroll
            for (int p = 0; p < NPAIRS_; p++) dl += hinge_s[bb][p];
            total += v / (float)C_ + dl / (float)NPAIRS_;
        }
        out[0] = total / (float)B_;
    }
}

extern "C" void kernel_launch(void* const* d_in, const int* in_sizes, int n_in,
                              void* d_out, int out_size) {
    const float* emb = (const float*)d_in[0];   // [8, 8, 1024, 1024] f32
    const int*   seg = (const int*)d_in[1];     // [8, 1024, 1024] i32
    (void)in_sizes; (void)n_in; (void)out_size;

    dim3 grid(CTAS_, B_);
    lane_loss_fused_kernel<<<grid, THREADS_>>>(emb, seg, (float*)d_out);
}

// round 10
// speedup vs baseline: 1.9901x; 1.0853x over previous
#include <cuda_runtime.h>
#include <cstdint>

// Problem constants (fixed by the dataset: emb [8,8,1024,1024] f32, gt_seg [8,1024,1024] i32)
#define B_      8
#define D_      8
#define HW_     (1024 * 1024)
#define C_      5
#define CTAS_   18            // CTAs per batch -> 144 total blocks (<=148 SMs, 1 wave)
#define THREADS_ 256
#define TOTAL_CTAS_ (CTAS_ * B_)
#define NVALS_  50
#define NPAIRS_ (C_ * (C_ - 1))   // 20 ordered pairs

// ---- TMA-bulk SMEM pipeline geometry ----
#define PXS_        1024                       // pixels per stage (4 per thread)
#define STAGES_PB_  (HW_ / PXS_)               // 1024 stages per batch
#define SEG_BYTES_  (PXS_ * 4)                 // 4 KB
#define ROW_BYTES_  (PXS_ * 4)                 // 4 KB per dim
#define STAGE_BYTES_ (SEG_BYTES_ + D_ * ROW_BYTES_)  // 36 KB
#define NS_         4                          // ring depth
#define MBAR_OFF_   0                          // NS_ pairs of (full, empty) mbarriers
#define DATA_OFF_   1024
#define SMEM_DYN_   (DATA_OFF_ + NS_ * STAGE_BYTES_)  // 148480 B

// NVALS layout per (batch, block):
//   [0..31]  S[c][d] c<4 | [32..39] T[d] | [40..43] q_c c<4 | [44] qT | [45..48] cnt_c c<4 | [49] n

typedef unsigned long long u64;

__device__ float g_partials[B_][CTAS_][NVALS_];
__device__ unsigned int g_done;   // zero at load; last block resets to 0 each launch

// ---- packed f32x2 helpers ----
__device__ __forceinline__ u64 pk2(float lo, float hi) {
    u64 r; asm("mov.b64 %0, {%1, %2};" : "=l"(r) : "f"(lo), "f"(hi)); return r;
}
__device__ __forceinline__ float2 upk2(u64 v) {
    float2 f; asm("mov.b64 {%0, %1}, %2;" : "=f"(f.x), "=f"(f.y) : "l"(v)); return f;
}
__device__ __forceinline__ void fma2(u64& a, u64 m, u64 v) {
    asm("fma.rn.f32x2 %0, %1, %2, %0;" : "+l"(a) : "l"(m), "l"(v));
}
__device__ __forceinline__ void add2(u64& a, u64 v) {
    asm("add.rn.f32x2 %0, %0, %1;" : "+l"(a) : "l"(v));
}

// ---- smem / mbarrier / bulk-copy helpers ----
__device__ __forceinline__ uint32_t smem_u32(const void* p) {
    uint32_t a; asm("{ .reg .u64 t; cvta.to.shared.u64 t, %1; cvt.u32.u64 %0, t; }" : "=r"(a) : "l"(p));
    return a;
}
__device__ __forceinline__ void mbar_init(uint32_t a, uint32_t cnt) {
    asm volatile("mbarrier.init.shared.b64 [%0], %1;" :: "r"(a), "r"(cnt) : "memory");
}
__device__ __forceinline__ void mbar_expect_tx(uint32_t a, uint32_t bytes) {
    asm volatile("mbarrier.arrive.expect_tx.shared.b64 _, [%0], %1;" :: "r"(a), "r"(bytes) : "memory");
}
__device__ __forceinline__ void mbar_arrive(uint32_t a) {
    asm volatile("mbarrier.arrive.shared.b64 _, [%0];" :: "r"(a) : "memory");
}
__device__ __forceinline__ void mbar_wait_acq(uint32_t a, uint32_t ph) {
    asm volatile(
        "{\n\t.reg .pred P;\n\t"
        "WL_%=:\n\t"
        "mbarrier.try_wait.parity.acquire.cta.shared::cta.b64 P, [%0], %1, 0x989680;\n\t"
        "@P bra.uni WD_%=;\n\t"
        "bra.uni WL_%=;\n\t"
        "WD_%=:\n\t}"
        :: "r"(a), "r"(ph) : "memory");
}
__device__ __forceinline__ void mbar_wait_rlx(uint32_t a, uint32_t ph) {
    asm volatile(
        "{\n\t.reg .pred P;\n\t"
        "WL_%=:\n\t"
        "mbarrier.try_wait.parity.relaxed.cta.shared::cta.b64 P, [%0], %1, 0x989680;\n\t"
        "@P bra.uni WD_%=;\n\t"
        "bra.uni WL_%=;\n\t"
        "WD_%=:\n\t}"
        :: "r"(a), "r"(ph) : "memory");
}
__device__ __forceinline__ void bulk_g2s(uint32_t dst, const void* src, uint32_t bytes, uint32_t mbar) {
    asm volatile("cp.async.bulk.shared::cta.global.mbarrier::complete_tx::bytes [%0], [%1], %2, [%3];"
                 :: "r"(dst), "l"(src), "r"(bytes), "r"(mbar) : "memory");
}

__device__ __forceinline__ void issue_stage(uint32_t sb, int slot, int st,
                                            const char* seg_g, const char* emb_g) {
    const uint32_t full = sb + MBAR_OFF_ + slot * 16;
    const uint32_t dst  = sb + DATA_OFF_ + slot * STAGE_BYTES_;
    const size_t px0 = (size_t)st * PXS_;
    mbar_expect_tx(full, STAGE_BYTES_);
    bulk_g2s(dst, seg_g + px0 * 4, SEG_BYTES_, full);
#pragma unroll
    for (int d = 0; d < D_; d++)
        bulk_g2s(dst + SEG_BYTES_ + d * ROW_BYTES_,
                 emb_g + ((size_t)d * HW_ + px0) * 4, ROW_BYTES_, full);
}

__global__ void __launch_bounds__(THREADS_, 1)
lane_loss_fused_kernel(const float* __restrict__ emb, const int* __restrict__ seg,
                       float* __restrict__ out) {
    extern __shared__ char smem[];
    const uint32_t sb = smem_u32(smem);
    const int b  = blockIdx.y;
    const int cj = blockIdx.x;
    const int tid = threadIdx.x;

    const char* seg_g = (const char*)(seg + (size_t)b * HW_);
    const char* emb_g = (const char*)(emb + (size_t)b * D_ * HW_);

    // barriers: full(slot) at +slot*16, empty(slot) at +slot*16+8
    if (tid == 0) {
#pragma unroll
        for (int s = 0; s < NS_; s++) {
            mbar_init(sb + MBAR_OFF_ + s * 16, 1);         // full: 1 arrive (expect_tx) + tx bytes
            mbar_init(sb + MBAR_OFF_ + s * 16 + 8, THREADS_); // empty: all consumers arrive
        }
    }
    __syncthreads();

    // Stages assigned to this CTA: st = cj + k*CTAS_, k = 0..nmine-1
    const int nmine = (STAGES_PB_ - cj + CTAS_ - 1) / CTAS_;   // 57 or 56 (>= NS_)

    // Producer prologue: fill the ring
    if (tid == 0) {
#pragma unroll
        for (int k = 0; k < NS_; k++)
            issue_stage(sb, k, cj + k * CTAS_, seg_g, emb_g);
    }

    // ---------------- Pass 1: pipelined streaming reduction ----------------
    u64 accS[4][D_], accT[D_], accQ[4], accQT, accC[4];
#pragma unroll
    for (int c = 0; c < 4; c++) { accQ[c] = 0ull; accC[c] = 0ull;
#pragma unroll
        for (int d = 0; d < D_; d++) accS[c][d] = 0ull; }
#pragma unroll
    for (int d = 0; d < D_; d++) accT[d] = 0ull;
    accQT = 0ull;

    int slot = 0, cons_ph = 0;       // consumer cursor
    int pslot = 0, prod_ph = 0;      // producer (reuse) cursor

    for (int k = 0; k < nmine; k++) {
        const uint32_t full  = sb + MBAR_OFF_ + slot * 16;
        const uint32_t empty = full + 8;
        mbar_wait_acq(full, cons_ph);

        const char* base = smem + DATA_OFF_ + slot * STAGE_BYTES_;
        const int4 s4 = *(const int4*)(base + tid * 16);

        u64 m01[4], m23[4];
#pragma unroll
        for (int c = 0; c < 4; c++) {
            m01[c] = pk2(s4.x == c ? 1.f : 0.f, s4.y == c ? 1.f : 0.f);
            m23[c] = pk2(s4.z == c ? 1.f : 0.f, s4.w == c ? 1.f : 0.f);
        }

        u64 q01 = 0ull, q23 = 0ull;
#pragma unroll
        for (int d = 0; d < D_; d++) {
            const float4 v = *(const float4*)(base + SEG_BYTES_ + d * ROW_BYTES_ + tid * 16);
            const u64 v01 = pk2(v.x, v.y);
            const u64 v23 = pk2(v.z, v.w);
            fma2(q01, v01, v01);
            fma2(q23, v23, v23);
            add2(accT[d], v01);
            add2(accT[d], v23);
#pragma unroll
            for (int c = 0; c < 4; c++) {
                fma2(accS[c][d], m01[c], v01);
                fma2(accS[c][d], m23[c], v23);
            }
        }
#pragma unroll
        for (int c = 0; c < 4; c++) {
            fma2(accQ[c], m01[c], q01);
            fma2(accQ[c], m23[c], q23);
            add2(accC[c], m01[c]);
            add2(accC[c], m23[c]);
        }
        add2(accQT, q01);
        add2(accQT, q23);

        mbar_arrive(empty);                     // this thread done reading the slot

        if (tid == 0 && k + NS_ < nmine) {      // refill the slot once all 256 arrived
            mbar_wait_rlx(sb + MBAR_OFF_ + pslot * 16 + 8, prod_ph);
            issue_stage(sb, pslot, cj + (k + NS_) * CTAS_, seg_g, emb_g);
            if (++pslot == NS_) { pslot = 0; prod_ph ^= 1; }
        }
        if (++slot == NS_) { slot = 0; cons_ph ^= 1; }
    }

    // Collapse packed lanes -> 50 per-thread scalars
    float vals[NVALS_];
#pragma unroll
    for (int c = 0; c < 4; c++)
#pragma unroll
        for (int d = 0; d < D_; d++) { float2 f = upk2(accS[c][d]); vals[c * D_ + d] = f.x + f.y; }
#pragma unroll
    for (int d = 0; d < D_; d++) { float2 f = upk2(accT[d]); vals[32 + d] = f.x + f.y; }
#pragma unroll
    for (int c = 0; c < 4; c++) { float2 f = upk2(accQ[c]); vals[40 + c] = f.x + f.y; }
    { float2 f = upk2(accQT); vals[44] = f.x + f.y; }
#pragma unroll
    for (int c = 0; c < 4; c++) { float2 f = upk2(accC[c]); vals[45 + c] = f.x + f.y; }
    vals[49] = (float)(nmine * 4);   // pixels per thread this block

    // Intra-warp butterfly reduce
#pragma unroll
    for (int kk = 0; kk < NVALS_; kk++)
#pragma unroll
        for (int off = 16; off > 0; off >>= 1)
            vals[kk] += __shfl_xor_sync(0xffffffffu, vals[kk], off);

    __shared__ float red[THREADS_ / 32][NVALS_];
    const int warp = tid >> 5, lane = tid & 31;
    if (lane == 0)
#pragma unroll
        for (int kk = 0; kk < NVALS_; kk++) red[warp][kk] = vals[kk];
    __syncthreads();
    if (tid < NVALS_) {
        float s = 0.f;
#pragma unroll
        for (int w = 0; w < THREADS_ / 32; w++) s += red[w][tid];
        g_partials[b][cj][tid] = s;
    }

    // ---------------- Last-block-done handoff ----------------
    __shared__ unsigned int amLast;
    __threadfence();
    if (tid == 0) {
        unsigned int v = atomicAdd(&g_done, 1u);
        amLast = (v == TOTAL_CTAS_ - 1) ? 1u : 0u;
    }
    __syncthreads();
    if (!amLast) return;
    __threadfence();
    if (tid == 0) g_done = 0;

    // ---------------- Pass 2: finalize (fp32, deterministic) ----------------
    __shared__ float sv[B_][NVALS_];
    __shared__ float mean_s[B_][C_][D_];
    __shared__ float sum_s[B_][C_][D_];
    __shared__ float var_s[B_][C_];
    __shared__ float hinge_s[B_][NPAIRS_];
    const int t = tid;

    for (int idx = t; idx < B_ * NVALS_; idx += THREADS_) {
        const int bb = idx / NVALS_, k = idx % NVALS_;
        float s = 0.f;
#pragma unroll
        for (int j = 0; j < CTAS_; j++) s += g_partials[bb][j][k];
        sv[bb][k] = s;
    }
    __syncthreads();

    for (int idx = t; idx < B_ * C_ * D_; idx += THREADS_) {
        const int bb = idx / (C_ * D_);
        const int c  = (idx / D_) % C_;
        const int d  = idx % D_;
        float sm, cn;
        if (c < 4) { sm = sv[bb][c * D_ + d]; cn = sv[bb][45 + c]; }
        else {
            sm = sv[bb][32 + d] - (sv[bb][0 * D_ + d] + sv[bb][1 * D_ + d] +
                                   sv[bb][2 * D_ + d] + sv[bb][3 * D_ + d]);
            cn = sv[bb][49] - (sv[bb][45] + sv[bb][46] + sv[bb][47] + sv[bb][48]);
        }
        sum_s[bb][c][d]  = sm;
        mean_s[bb][c][d] = sm / cn;
    }
    __syncthreads();

    for (int idx = t; idx < B_ * C_; idx += THREADS_) {
        const int bb = idx / C_, c = idx % C_;
        float q;
        if (c < 4) q = sv[bb][40 + c];
        else       q = sv[bb][44] - (sv[bb][40] + sv[bb][41] + sv[bb][42] + sv[bb][43]);
        float m2 = 0.f;
#pragma unroll
        for (int d = 0; d < D_; d++) m2 += sum_s[bb][c][d] * mean_s[bb][c][d];
        float ssv = q - m2;
        if (ssv < 0.f) ssv = 0.f;
        const float r = sqrtf(ssv) - 0.5f;           // SIGMA_V
        var_s[bb][c] = r > 0.f ? r : 0.f;
    }

    for (int idx = t; idx < B_ * NPAIRS_; idx += THREADS_) {
        const int bb = idx / NPAIRS_, p = idx % NPAIRS_;
        const int i = p / (C_ - 1);
        int j = p % (C_ - 1);
        if (j >= i) j++;
        float d2 = 0.f;
#pragma unroll
        for (int d = 0; d < D_; d++) {
            const float df = mean_s[bb][i][d] - mean_s[bb][j][d];
            d2 += df * df;
        }
        const float h = 3.0f - sqrtf(d2);            // SIGMA_D
        hinge_s[bb][p] = h > 0.f ? h : 0.f;
    }
    __syncthreads();

    if (t == 0) {
        float total = 0.f;
        for (int bb = 0; bb < B_; bb++) {
            float v = 0.f;
#pragma unroll
            for (int c = 0; c < C_; c++) v += var_s[bb][c];
            float dl = 0.f;
#pragma unroll
            for (int p = 0; p < NPAIRS_; p++) dl += hinge_s[bb][p];
            total += v / (float)C_ + dl / (float)NPAIRS_;
        }
        out[0] = total / (float)B_;
    }
}

extern "C" void kernel_launch(void* const* d_in, const int* in_sizes, int n_in,
                              void* d_out, int out_size) {
    const float* emb = (const float*)d_in[0];   // [8, 8, 1024, 1024] f32
    const int*   seg = (const int*)d_in[1];     // [8, 1024, 1024] i32
    (void)in_sizes; (void)n_in; (void)out_size;

    cudaFuncSetAttribute(lane_loss_fused_kernel,
                         cudaFuncAttributeMaxDynamicSharedMemorySize, SMEM_DYN_);
    dim3 grid(CTAS_, B_);
    lane_loss_fused_kernel<<<grid, THREADS_, SMEM_DYN_>>>(emb, seg, (float*)d_out);
}

// round 11
// speedup vs baseline: 1.9913x; 1.0006x over previous
#include <cuda_runtime.h>
#include <cstdint>

// Problem constants (fixed by the dataset: emb [8,8,1024,1024] f32, gt_seg [8,1024,1024] i32)
#define B_      8
#define D_      8
#define HW_     (1024 * 1024)
#define C_      5
#define CTAS_   18            // CTAs per batch -> 144 total blocks (<=148 SMs, 1 wave)
#define THREADS_ 256
#define NWARPS_ (THREADS_ / 32)
#define TOTAL_CTAS_ (CTAS_ * B_)
#define NVALS_  50
#define NPAIRS_ (C_ * (C_ - 1))   // 20 ordered pairs

// ---- TMA-bulk SMEM pipeline geometry ----
#define PXS_        1024                       // pixels per stage (4 per thread)
#define STAGES_PB_  (HW_ / PXS_)               // 1024 stages per batch
#define SEG_BYTES_  (PXS_ * 4)                 // 4 KB
#define ROW_BYTES_  (PXS_ * 4)                 // 4 KB per dim
#define STAGE_BYTES_ (SEG_BYTES_ + D_ * ROW_BYTES_)  // 36 KB
#define NS_         4                          // ring depth
#define MBAR_OFF_   0                          // NS_ pairs of (full, empty) mbarriers
#define DATA_OFF_   1024
#define SMEM_DYN_   (DATA_OFF_ + NS_ * STAGE_BYTES_)  // 148480 B

// NVALS layout per (batch, block):
//   [0..31]  S[c][d] c<4 | [32..39] T[d] | [40..43] q_c c<4 | [44] qT | [45..48] cnt_c c<4 | [49] n

typedef unsigned long long u64;

__device__ float g_partials[B_][CTAS_][NVALS_];
__device__ unsigned int g_done;   // zero at load; last block resets to 0 each launch

// ---- packed f32x2 helpers ----
__device__ __forceinline__ u64 pk2(float lo, float hi) {
    u64 r; asm("mov.b64 %0, {%1, %2};" : "=l"(r) : "f"(lo), "f"(hi)); return r;
}
__device__ __forceinline__ float2 upk2(u64 v) {
    float2 f; asm("mov.b64 {%0, %1}, %2;" : "=f"(f.x), "=f"(f.y) : "l"(v)); return f;
}
__device__ __forceinline__ void fma2(u64& a, u64 m, u64 v) {
    asm("fma.rn.f32x2 %0, %1, %2, %0;" : "+l"(a) : "l"(m), "l"(v));
}
__device__ __forceinline__ void add2(u64& a, u64 v) {
    asm("add.rn.f32x2 %0, %0, %1;" : "+l"(a) : "l"(v));
}

// ---- smem / mbarrier / bulk-copy helpers ----
__device__ __forceinline__ uint32_t smem_u32(const void* p) {
    uint32_t a; asm("{ .reg .u64 t; cvta.to.shared.u64 t, %1; cvt.u32.u64 %0, t; }" : "=r"(a) : "l"(p));
    return a;
}
__device__ __forceinline__ void mbar_init(uint32_t a, uint32_t cnt) {
    asm volatile("mbarrier.init.shared.b64 [%0], %1;" :: "r"(a), "r"(cnt) : "memory");
}
__device__ __forceinline__ void mbar_expect_tx(uint32_t a, uint32_t bytes) {
    asm volatile("mbarrier.arrive.expect_tx.shared.b64 _, [%0], %1;" :: "r"(a), "r"(bytes) : "memory");
}
__device__ __forceinline__ void mbar_arrive(uint32_t a) {
    asm volatile("mbarrier.arrive.shared.b64 _, [%0];" :: "r"(a) : "memory");
}
__device__ __forceinline__ void mbar_wait_acq(uint32_t a, uint32_t ph) {
    asm volatile(
        "{\n\t.reg .pred P;\n\t"
        "WL_%=:\n\t"
        "mbarrier.try_wait.parity.acquire.cta.shared::cta.b64 P, [%0], %1, 0x989680;\n\t"
        "@P bra.uni WD_%=;\n\t"
        "bra.uni WL_%=;\n\t"
        "WD_%=:\n\t}"
        :: "r"(a), "r"(ph) : "memory");
}
__device__ __forceinline__ void mbar_wait_rlx(uint32_t a, uint32_t ph) {
    asm volatile(
        "{\n\t.reg .pred P;\n\t"
        "WL_%=:\n\t"
        "mbarrier.try_wait.parity.relaxed.cta.shared::cta.b64 P, [%0], %1, 0x989680;\n\t"
        "@P bra.uni WD_%=;\n\t"
        "bra.uni WL_%=;\n\t"
        "WD_%=:\n\t}"
        :: "r"(a), "r"(ph) : "memory");
}
__device__ __forceinline__ void bulk_g2s(uint32_t dst, const void* src, uint32_t bytes, uint32_t mbar) {
    asm volatile("cp.async.bulk.shared::cta.global.mbarrier::complete_tx::bytes [%0], [%1], %2, [%3];"
                 :: "r"(dst), "l"(src), "r"(bytes), "r"(mbar) : "memory");
}

__device__ __forceinline__ void issue_stage(uint32_t sb, int slot, int st,
                                            const char* seg_g, const char* emb_g) {
    const uint32_t full = sb + MBAR_OFF_ + slot * 16;
    const uint32_t dst  = sb + DATA_OFF_ + slot * STAGE_BYTES_;
    const size_t px0 = (size_t)st * PXS_;
    mbar_expect_tx(full, STAGE_BYTES_);
    bulk_g2s(dst, seg_g + px0 * 4, SEG_BYTES_, full);
#pragma unroll
    for (int d = 0; d < D_; d++)
        bulk_g2s(dst + SEG_BYTES_ + d * ROW_BYTES_,
                 emb_g + ((size_t)d * HW_ + px0) * 4, ROW_BYTES_, full);
}

__global__ void __launch_bounds__(THREADS_, 1)
lane_loss_fused_kernel(const float* __restrict__ emb, const int* __restrict__ seg,
                       float* __restrict__ out) {
    extern __shared__ char smem[];
    const uint32_t sb = smem_u32(smem);
    const int b  = blockIdx.y;
    const int cj = blockIdx.x;
    const int tid = threadIdx.x;
    const int lane = tid & 31;

    const char* seg_g = (const char*)(seg + (size_t)b * HW_);
    const char* emb_g = (const char*)(emb + (size_t)b * D_ * HW_);

    // barriers: full(slot) at +slot*16, empty(slot) at +slot*16+8
    if (tid == 0) {
#pragma unroll
        for (int s = 0; s < NS_; s++) {
            mbar_init(sb + MBAR_OFF_ + s * 16, 1);        // full: 1 expect_tx arrive + tx bytes
            mbar_init(sb + MBAR_OFF_ + s * 16 + 8, NWARPS_); // empty: one elected arrive per warp
        }
    }
    __syncthreads();

    // Stages assigned to this CTA: st = cj + k*CTAS_, k = 0..nmine-1
    const int nmine = (STAGES_PB_ - cj + CTAS_ - 1) / CTAS_;   // 57 or 56 (>= NS_)

    // Producer prologue: fill the ring
    if (tid == 0) {
#pragma unroll
        for (int k = 0; k < NS_; k++)
            issue_stage(sb, k, cj + k * CTAS_, seg_g, emb_g);
    }

    // ---------------- Pass 1: pipelined streaming reduction ----------------
    u64 accS[4][D_], accT[D_], accQ[4], accQT, accC[4];
#pragma unroll
    for (int c = 0; c < 4; c++) { accQ[c] = 0ull; accC[c] = 0ull;
#pragma unroll
        for (int d = 0; d < D_; d++) accS[c][d] = 0ull; }
#pragma unroll
    for (int d = 0; d < D_; d++) accT[d] = 0ull;
    accQT = 0ull;

    int slot = 0, ph = 0;            // shared cursor: refill slot == consume slot

    for (int k = 0; k < nmine; k++) {
        const uint32_t full  = sb + MBAR_OFF_ + slot * 16;
        const uint32_t empty = full + 8;
        mbar_wait_acq(full, ph);

        // (a) Drain the stage into registers first (144 B/thread)
        const char* base = smem + DATA_OFF_ + slot * STAGE_BYTES_;
        const int4 s4 = *(const int4*)(base + tid * 16);
        float4 v[D_];
#pragma unroll
        for (int d = 0; d < D_; d++)
            v[d] = *(const float4*)(base + SEG_BYTES_ + d * ROW_BYTES_ + tid * 16);

        // (b) Release the slot immediately — one elected arrive per warp
        __syncwarp();
        if (lane == 0) mbar_arrive(empty);

        // (c) Refill this slot with stage k+NS right away (gated on loads, not compute)
        if (tid == 0 && k + NS_ < nmine) {
            mbar_wait_rlx(empty, ph);          // empty phase cadence == full phase cadence
            issue_stage(sb, slot, cj + (k + NS_) * CTAS_, seg_g, emb_g);
        }

        // (d) Compute from registers
        u64 m01[4], m23[4];
#pragma unroll
        for (int c = 0; c < 4; c++) {
            m01[c] = pk2(s4.x == c ? 1.f : 0.f, s4.y == c ? 1.f : 0.f);
            m23[c] = pk2(s4.z == c ? 1.f : 0.f, s4.w == c ? 1.f : 0.f);
        }

        u64 q01 = 0ull, q23 = 0ull;
#pragma unroll
        for (int d = 0; d < D_; d++) {
            const u64 v01 = pk2(v[d].x, v[d].y);
            const u64 v23 = pk2(v[d].z, v[d].w);
            fma2(q01, v01, v01);
            fma2(q23, v23, v23);
            add2(accT[d], v01);
            add2(accT[d], v23);
#pragma unroll
            for (int c = 0; c < 4; c++) {
                fma2(accS[c][d], m01[c], v01);
                fma2(accS[c][d], m23[c], v23);
            }
        }
#pragma unroll
        for (int c = 0; c < 4; c++) {
            fma2(accQ[c], m01[c], q01);
            fma2(accQ[c], m23[c], q23);
            add2(accC[c], m01[c]);
            add2(accC[c], m23[c]);
        }
        add2(accQT, q01);
        add2(accQT, q23);

        if (++slot == NS_) { slot = 0; ph ^= 1; }
    }

    // Collapse packed lanes -> 50 per-thread scalars
    float vals[NVALS_];
#pragma unroll
    for (int c = 0; c < 4; c++)
#pragma unroll
        for (int d = 0; d < D_; d++) { float2 f = upk2(accS[c][d]); vals[c * D_ + d] = f.x + f.y; }
#pragma unroll
    for (int d = 0; d < D_; d++) { float2 f = upk2(accT[d]); vals[32 + d] = f.x + f.y; }
#pragma unroll
    for (int c = 0; c < 4; c++) { float2 f = upk2(accQ[c]); vals[40 + c] = f.x + f.y; }
    { float2 f = upk2(accQT); vals[44] = f.x + f.y; }
#pragma unroll
    for (int c = 0; c < 4; c++) { float2 f = upk2(accC[c]); vals[45 + c] = f.x + f.y; }
    vals[49] = (float)(nmine * 4);   // pixels per thread this block

    // Intra-warp butterfly reduce
#pragma unroll
    for (int kk = 0; kk < NVALS_; kk++)
#pragma unroll
        for (int off = 16; off > 0; off >>= 1)
            vals[kk] += __shfl_xor_sync(0xffffffffu, vals[kk], off);

    __shared__ float red[NWARPS_][NVALS_];
    const int warp = tid >> 5;
    if (lane == 0)
#pragma unroll
        for (int kk = 0; kk < NVALS_; kk++) red[warp][kk] = vals[kk];
    __syncthreads();
    if (tid < NVALS_) {
        float s = 0.f;
#pragma unroll
        for (int w = 0; w < NWARPS_; w++) s += red[w][tid];
        g_partials[b][cj][tid] = s;
    }

    // ---------------- Last-block-done handoff ----------------
    __shared__ unsigned int amLast;
    __threadfence();
    if (tid == 0) {
        unsigned int v = atomicAdd(&g_done, 1u);
        amLast = (v == TOTAL_CTAS_ - 1) ? 1u : 0u;
    }
    __syncthreads();
    if (!amLast) return;
    __threadfence();
    if (tid == 0) g_done = 0;

    // ---------------- Pass 2: finalize (fp32, deterministic) ----------------
    __shared__ float sv[B_][NVALS_];
    __shared__ float mean_s[B_][C_][D_];
    __shared__ float sum_s[B_][C_][D_];
    __shared__ float var_s[B_][C_];
    __shared__ float hinge_s[B_][NPAIRS_];
    const int t = tid;

    for (int idx = t; idx < B_ * NVALS_; idx += THREADS_) {
        const int bb = idx / NVALS_, kk = idx % NVALS_;
        float s = 0.f;
#pragma unroll
        for (int j = 0; j < CTAS_; j++) s += g_partials[bb][j][kk];
        sv[bb][kk] = s;
    }
    __syncthreads();

    for (int idx = t; idx < B_ * C_ * D_; idx += THREADS_) {
        const int bb = idx / (C_ * D_);
        const int c  = (idx / D_) % C_;
        const int d  = idx % D_;
        float sm, cn;
        if (c < 4) { sm = sv[bb][c * D_ + d]; cn = sv[bb][45 + c]; }
        else {
            sm = sv[bb][32 + d] - (sv[bb][0 * D_ + d] + sv[bb][1 * D_ + d] +
                                   sv[bb][2 * D_ + d] + sv[bb][3 * D_ + d]);
            cn = sv[bb][49] - (sv[bb][45] + sv[bb][46] + sv[bb][47] + sv[bb][48]);
        }
        sum_s[bb][c][d]  = sm;
        mean_s[bb][c][d] = sm / cn;
    }
    __syncthreads();

    for (int idx = t; idx < B_ * C_; idx += THREADS_) {
        const int bb = idx / C_, c = idx % C_;
        float q;
        if (c < 4) q = sv[bb][40 + c];
        else       q = sv[bb][44] - (sv[bb][40] + sv[bb][41] + sv[bb][42] + sv[bb][43]);
        float m2 = 0.f;
#pragma unroll
        for (int d = 0; d < D_; d++) m2 += sum_s[bb][c][d] * mean_s[bb][c][d];
        float ssv = q - m2;
        if (ssv < 0.f) ssv = 0.f;
        const float r = sqrtf(ssv) - 0.5f;           // SIGMA_V
        var_s[bb][c] = r > 0.f ? r : 0.f;
    }

    for (int idx = t; idx < B_ * NPAIRS_; idx += THREADS_) {
        const int bb = idx / NPAIRS_, p = idx % NPAIRS_;
        const int i = p / (C_ - 1);
        int j = p % (C_ - 1);
        if (j >= i) j++;
        float d2 = 0.f;
#pragma unroll
        for (int d = 0; d < D_; d++) {
            const float df = mean_s[bb][i][d] - mean_s[bb][j][d];
            d2 += df * df;
        }
        const float h = 3.0f - sqrtf(d2);            // SIGMA_D
        hinge_s[bb][p] = h > 0.f ? h : 0.f;
    }
    __syncthreads();

    if (t == 0) {
        float total = 0.f;
        for (int bb = 0; bb < B_; bb++) {
            float v = 0.f;
#pragma unroll
            for (int c = 0; c < C_; c++) v += var_s[bb][c];
            float dl = 0.f;
#pragma unroll
            for (int p = 0; p < NPAIRS_; p++) dl += hinge_s[bb][p];
            total += v / (float)C_ + dl / (float)NPAIRS_;
        }
        out[0] = total / (float)B_;
    }
}

extern "C" void kernel_launch(void* const* d_in, const int* in_sizes, int n_in,
                              void* d_out, int out_size) {
    const float* emb = (const float*)d_in[0];   // [8, 8, 1024, 1024] f32
    const int*   seg = (const int*)d_in[1];     // [8, 1024, 1024] i32
    (void)in_sizes; (void)n_in; (void)out_size;

    cudaFuncSetAttribute(lane_loss_fused_kernel,
                         cudaFuncAttributeMaxDynamicSharedMemorySize, SMEM_DYN_);
    dim3 grid(CTAS_, B_);
    lane_loss_fused_kernel<<<grid, THREADS_, SMEM_DYN_>>>(emb, seg, (float*)d_out);
}